// round 9
// baseline (speedup 1.0000x reference)
#include <cuda_runtime.h>
#include <cuda_bf16.h>
#include <cstdint>

// Problem dims (fixed by the dataset)
#define B_DIM 8192
#define DIN   1024
#define H_DIM 2048

// Tiling: 128x128 CTA tile, 4 warps (warp tile 64x64), 2 CTAs per SM
#define BM 128
#define BN 128
#define BKE 64          // bf16 K-elements per chunk = 128B rows (swizzle atom)
#define NK 48           // 3072 / 64
#define NKX 16          // first 16 chunks: x / win (K=1024)
#define STAGES 3
#define NTHREADS 128    // 4 warps, warp tile 64x64

#define A_BYTES (BM * 128)                 // 16 KB
#define B_BYTES (BN * 128)                 // 16 KB
#define STAGE_BYTES (A_BYTES + B_BYTES)    // 32 KB
#define SMEM_TOTAL (STAGES * STAGE_BYTES)  // 96 KB  (x2 CTAs = 192 KB/SM)

// bf16 copies of the inputs (static scratch; no allocation allowed)
__device__ __nv_bfloat16 g_xb[(size_t)B_DIM * DIN];
__device__ __nv_bfloat16 g_ub[(size_t)B_DIM * H_DIM];
__device__ __nv_bfloat16 g_winb[(size_t)H_DIM * DIN];
__device__ __nv_bfloat16 g_wrb[(size_t)H_DIM * H_DIM];

__device__ __forceinline__ uint32_t smem_u32(const void* p) {
    uint32_t a;
    asm("{ .reg .u64 t; cvta.to.shared.u64 t, %1; cvt.u32.u64 %0, t; }"
        : "=r"(a) : "l"(p));
    return a;
}

__device__ __forceinline__ void cp_async16(uint32_t saddr, const void* g) {
    asm volatile("cp.async.cg.shared.global [%0], [%1], 16;\n"
                 :: "r"(saddr), "l"(g));
}

__device__ __forceinline__ void cp_commit() {
    asm volatile("cp.async.commit_group;\n" ::: "memory");
}

template <int N>
__device__ __forceinline__ void cp_wait() {
    asm volatile("cp.async.wait_group %0;\n" :: "n"(N) : "memory");
}

#define LDSM_X4(r, addr) \
    asm volatile("ldmatrix.sync.aligned.m8n8.x4.shared.b16 {%0,%1,%2,%3}, [%4];" \
        : "=r"((r)[0]), "=r"((r)[1]), "=r"((r)[2]), "=r"((r)[3]) : "r"(addr))

__device__ __forceinline__ void mma_bf16(float* c, const uint32_t* a,
                                         uint32_t b0, uint32_t b1) {
    asm volatile(
        "mma.sync.aligned.m16n8k16.row.col.f32.bf16.bf16.f32 "
        "{%0,%1,%2,%3}, {%4,%5,%6,%7}, {%8,%9}, {%0,%1,%2,%3};"
        : "+f"(c[0]), "+f"(c[1]), "+f"(c[2]), "+f"(c[3])
        : "r"(a[0]), "r"(a[1]), "r"(a[2]), "r"(a[3]), "r"(b0), "r"(b1));
}

// ---------------------------------------------------------------------------
// fp32 -> bf16 conversion pre-pass (one float4 per thread)
// ---------------------------------------------------------------------------
#define SX4 ((size_t)B_DIM * DIN / 4)     // 2,097,152
#define SU4 ((size_t)B_DIM * H_DIM / 4)   // 4,194,304
#define SW4 ((size_t)H_DIM * DIN / 4)     //   524,288
#define SR4 ((size_t)H_DIM * H_DIM / 4)   // 1,048,576
#define TOTAL4 (SX4 + SU4 + SW4 + SR4)    // 7,864,320

__global__ void __launch_bounds__(256)
convert_kernel(const float4* __restrict__ x, const float4* __restrict__ u,
               const float4* __restrict__ win, const float4* __restrict__ wr) {
    const size_t i = (size_t)blockIdx.x * blockDim.x + threadIdx.x;
    float4 f;
    __nv_bfloat16* dst;
    size_t j;
    if (i < SX4)                   { j = i;                   f = x[j];   dst = g_xb;   }
    else if (i < SX4 + SU4)        { j = i - SX4;             f = u[j];   dst = g_ub;   }
    else if (i < SX4 + SU4 + SW4)  { j = i - SX4 - SU4;       f = win[j]; dst = g_winb; }
    else if (i < TOTAL4)           { j = i - SX4 - SU4 - SW4; f = wr[j];  dst = g_wrb;  }
    else return;
    __nv_bfloat162* o = reinterpret_cast<__nv_bfloat162*>(dst) + j * 2;
    o[0] = __floats2bfloat162_rn(f.x, f.y);
    o[1] = __floats2bfloat162_rn(f.z, f.w);
}

// ---------------------------------------------------------------------------
// Fused GEMM + SfaRNN epilogue (128x128 tile, 4 warps 64x64, 2 CTAs/SM)
// ---------------------------------------------------------------------------
__global__ void __launch_bounds__(NTHREADS, 2)
sfa_rnn_kernel(const float* __restrict__ u,
               const float* __restrict__ v,
               const float* __restrict__ bias,
               float* __restrict__ out) {
    extern __shared__ char smem[];
    const uint32_t sbase = smem_u32(smem);

    const int tid  = threadIdx.x;
    const int wid  = tid >> 5;
    const int lane = tid & 31;
    const int lq   = lane >> 2;
    const int lr   = lane & 3;
    const int wm   = wid & 1;    // M half (64 rows)
    const int wn   = wid >> 1;   // N half (64 cols)

    const int nb = blockIdx.x * BN;
    const int mb = blockIdx.y * BM;

    // ---------------- producer geometry ----------------
    // Per chunk: A 16KB + B 16KB = 2048 x 16B; 128 threads -> 16 each (8 A + 8 B)
    const int rbase = tid >> 3;  // 0..15
    const int c16   = tid & 7;   // 16B chunk within 128B row
    const uint32_t swbase =
        (uint32_t)rbase * 128u + ((uint32_t)(c16 ^ (rbase & 7)) << 4);

    const __nv_bfloat16* gax = g_xb   + (size_t)(mb + rbase) * DIN   + c16 * 8;
    const __nv_bfloat16* gau = g_ub   + (size_t)(mb + rbase) * H_DIM + c16 * 8;
    const __nv_bfloat16* gbw = g_winb + (size_t)(nb + rbase) * DIN   + c16 * 8;
    const __nv_bfloat16* gbr = g_wrb  + (size_t)(nb + rbase) * H_DIM + c16 * 8;

    auto issue_chunk = [&](int k) {
        const int s = k % STAGES;
        const uint32_t sA = sbase + s * STAGE_BYTES;
        const uint32_t sB = sA + A_BYTES;
        if (k < NKX) {
            const __nv_bfloat16* ga = gax + k * BKE;
            const __nv_bfloat16* gb = gbw + k * BKE;
#pragma unroll
            for (int i = 0; i < 8; i++)
                cp_async16(sA + swbase + i * 2048u, ga + (size_t)i * 16 * DIN);
#pragma unroll
            for (int i = 0; i < 8; i++)
                cp_async16(sB + swbase + i * 2048u, gb + (size_t)i * 16 * DIN);
        } else {
            const __nv_bfloat16* ga = gau + (k - NKX) * BKE;
            const __nv_bfloat16* gb = gbr + (k - NKX) * BKE;
#pragma unroll
            for (int i = 0; i < 8; i++)
                cp_async16(sA + swbase + i * 2048u, ga + (size_t)i * 16 * H_DIM);
#pragma unroll
            for (int i = 0; i < 8; i++)
                cp_async16(sB + swbase + i * 2048u, gb + (size_t)i * 16 * H_DIM);
        }
    };

    // ---------------- consumer geometry (ldmatrix) ----------------
    const uint32_t r8   = (uint32_t)(lane & 7);
    const uint32_t a_hi = (uint32_t)(lane >> 4);
    const uint32_t a_m8 = (uint32_t)(((lane >> 3) & 1) << 3);
    const uint32_t b_hi = (uint32_t)((lane >> 3) & 1);
    const uint32_t b_n8 = (uint32_t)((lane >> 4) << 3);

    uint32_t baseA[4];
#pragma unroll
    for (int mi = 0; mi < 4; mi++)
        baseA[mi] = (uint32_t)(wm * 64 + mi * 16) * 128u + (r8 + a_m8) * 128u;
    uint32_t baseB[4];
#pragma unroll
    for (int ni2 = 0; ni2 < 4; ni2++)
        baseB[ni2] = (uint32_t)(wn * 64 + ni2 * 16) * 128u + (r8 + b_n8) * 128u;

    float acc[4][8][4];
#pragma unroll
    for (int mi = 0; mi < 4; mi++)
#pragma unroll
        for (int ni = 0; ni < 8; ni++)
#pragma unroll
            for (int r = 0; r < 4; r++) acc[mi][ni][r] = 0.0f;

    // ---------------- prologue ----------------
    issue_chunk(0); cp_commit();
    issue_chunk(1); cp_commit();

    // ---------------- mainloop ----------------
#pragma unroll 1
    for (int k = 0; k < NK; k++) {
        cp_wait<1>();
        __syncthreads();
        if (k + 2 < NK) issue_chunk(k + 2);
        cp_commit();

        const int s = k % STAGES;
        const uint32_t sA = sbase + s * STAGE_BYTES;
        const uint32_t sB = sA + A_BYTES;

#pragma unroll
        for (int ks = 0; ks < 4; ks++) {
            const uint32_t offA = (((uint32_t)(2 * ks) + a_hi) ^ r8) << 4;
            const uint32_t offB = (((uint32_t)(2 * ks) + b_hi) ^ r8) << 4;

            uint32_t a[4][4];
#pragma unroll
            for (int mi = 0; mi < 4; mi++) LDSM_X4(a[mi], sA + baseA[mi] + offA);
            uint32_t b[4][4];
#pragma unroll
            for (int ni2 = 0; ni2 < 4; ni2++) LDSM_X4(b[ni2], sB + baseB[ni2] + offB);

#pragma unroll
            for (int mi = 0; mi < 4; mi++)
#pragma unroll
                for (int ni = 0; ni < 8; ni++)
                    mma_bf16(acc[mi][ni], a[mi],
                             b[ni >> 1][(ni & 1) * 2 + 0],
                             b[ni >> 1][(ni & 1) * 2 + 1]);
        }
    }

    // ---------------- fused epilogue ----------------
    const float cu  = 1.0f - (1.0f / 10.0f);
    const float au  = 1.0f / 10.0f;
    const float cv  = 1.0f - (1.0f / 150.0f);
    const float cvm = 10.0f / 150.0f;
    const size_t OUTV = (size_t)B_DIM * H_DIM;

#pragma unroll
    for (int mi = 0; mi < 4; mi++) {
#pragma unroll
        for (int ni = 0; ni < 8; ni++) {
            const int r0 = mb + wm * 64 + mi * 16 + lq;
            const int c  = nb + wn * 64 + ni * 8 + lr * 2;
            const float2 bn = *reinterpret_cast<const float2*>(bias + c);
#pragma unroll
            for (int h = 0; h < 2; h++) {
                const size_t off = (size_t)(r0 + 8 * h) * H_DIM + c;
                const float2 uu = *reinterpret_cast<const float2*>(u + off);
                const float2 vv = *reinterpret_cast<const float2*>(v + off);
                const float g0 = acc[mi][ni][2 * h + 0];
                const float g1 = acc[mi][ni][2 * h + 1];
                const float vn0 = fmaxf(cv * vv.x + cvm * uu.x, 0.0f);
                const float vn1 = fmaxf(cv * vv.y + cvm * uu.y, 0.0f);
                const float un0 = fmaxf(cu * uu.x + au * (g0 + bn.x - vn0), 0.0f);
                const float un1 = fmaxf(cu * uu.y + au * (g1 + bn.y - vn1), 0.0f);
                *reinterpret_cast<float2*>(out + off)        = make_float2(un0, un1);
                *reinterpret_cast<float2*>(out + OUTV + off) = make_float2(vn0, vn1);
            }
        }
    }
}

extern "C" void kernel_launch(void* const* d_in, const int* in_sizes, int n_in,
                              void* d_out, int out_size) {
    (void)in_sizes; (void)n_in; (void)out_size;
    const float* x    = (const float*)d_in[0];
    const float* u    = (const float*)d_in[1];
    const float* v    = (const float*)d_in[2];
    const float* win  = (const float*)d_in[3];
    const float* wr   = (const float*)d_in[4];
    const float* bias = (const float*)d_in[5];
    float* out = (float*)d_out;

    // 1) convert inputs to bf16 scratch
    const int cb = (int)(TOTAL4 / 256);  // 30720 blocks, exact
    convert_kernel<<<cb, 256>>>((const float4*)x, (const float4*)u,
                                (const float4*)win, (const float4*)wr);

    // 2) fused GEMM + epilogue
    cudaFuncSetAttribute(sfa_rnn_kernel,
                         cudaFuncAttributeMaxDynamicSharedMemorySize, SMEM_TOTAL);
    dim3 grid(H_DIM / BN, B_DIM / BM);  // (16, 64) = 1024 CTAs
    sfa_rnn_kernel<<<grid, NTHREADS, SMEM_TOTAL>>>(u, v, bias, out);
}

// round 10
// speedup vs baseline: 1.5253x; 1.5253x over previous
#include <cuda_runtime.h>
#include <cuda_bf16.h>
#include <cstdint>

// Problem dims (fixed by the dataset)
#define B_DIM 8192
#define DIN   1024
#define H_DIM 2048

// Tiling: 128x128 CTA tile, 8 warps (warp tile 64x32), 2 CTAs per SM
#define BM 128
#define BN 128
#define BKE 64          // bf16 K-elements per chunk = 128B rows (swizzle atom)
#define NK 48           // 3072 / 64
#define NKX 16          // first 16 chunks: x / win (K=1024)
#define STAGES 3
#define NTHREADS 256    // 8 warps, warp tile 64x32

#define A_BYTES (BM * 128)                 // 16 KB
#define B_BYTES (BN * 128)                 // 16 KB
#define STAGE_BYTES (A_BYTES + B_BYTES)    // 32 KB
#define SMEM_TOTAL (STAGES * STAGE_BYTES)  // 96 KB  (x2 CTAs = 192 KB/SM)

// bf16 copies of the inputs (static scratch; no allocation allowed)
__device__ __nv_bfloat16 g_xb[(size_t)B_DIM * DIN];
__device__ __nv_bfloat16 g_ub[(size_t)B_DIM * H_DIM];
__device__ __nv_bfloat16 g_winb[(size_t)H_DIM * DIN];
__device__ __nv_bfloat16 g_wrb[(size_t)H_DIM * H_DIM];

__device__ __forceinline__ uint32_t smem_u32(const void* p) {
    uint32_t a;
    asm("{ .reg .u64 t; cvta.to.shared.u64 t, %1; cvt.u32.u64 %0, t; }"
        : "=r"(a) : "l"(p));
    return a;
}

__device__ __forceinline__ void cp_async16(uint32_t saddr, const void* g) {
    asm volatile("cp.async.cg.shared.global [%0], [%1], 16;\n"
                 :: "r"(saddr), "l"(g));
}

__device__ __forceinline__ void cp_commit() {
    asm volatile("cp.async.commit_group;\n" ::: "memory");
}

template <int N>
__device__ __forceinline__ void cp_wait() {
    asm volatile("cp.async.wait_group %0;\n" :: "n"(N) : "memory");
}

#define LDSM_X4(r, addr) \
    asm volatile("ldmatrix.sync.aligned.m8n8.x4.shared.b16 {%0,%1,%2,%3}, [%4];" \
        : "=r"((r)[0]), "=r"((r)[1]), "=r"((r)[2]), "=r"((r)[3]) : "r"(addr))

__device__ __forceinline__ void mma_bf16(float* c, const uint32_t* a,
                                         uint32_t b0, uint32_t b1) {
    asm volatile(
        "mma.sync.aligned.m16n8k16.row.col.f32.bf16.bf16.f32 "
        "{%0,%1,%2,%3}, {%4,%5,%6,%7}, {%8,%9}, {%0,%1,%2,%3};"
        : "+f"(c[0]), "+f"(c[1]), "+f"(c[2]), "+f"(c[3])
        : "r"(a[0]), "r"(a[1]), "r"(a[2]), "r"(a[3]), "r"(b0), "r"(b1));
}

// ---------------------------------------------------------------------------
// fp32 -> bf16 conversion pre-pass (one float4 per thread)
// ---------------------------------------------------------------------------
#define SX4 ((size_t)B_DIM * DIN / 4)     // 2,097,152
#define SU4 ((size_t)B_DIM * H_DIM / 4)   // 4,194,304
#define SW4 ((size_t)H_DIM * DIN / 4)     //   524,288
#define SR4 ((size_t)H_DIM * H_DIM / 4)   // 1,048,576
#define TOTAL4 (SX4 + SU4 + SW4 + SR4)    // 7,864,320

__global__ void __launch_bounds__(256)
convert_kernel(const float4* __restrict__ x, const float4* __restrict__ u,
               const float4* __restrict__ win, const float4* __restrict__ wr) {
    const size_t i = (size_t)blockIdx.x * blockDim.x + threadIdx.x;
    float4 f;
    __nv_bfloat16* dst;
    size_t j;
    if (i < SX4)                   { j = i;                   f = x[j];   dst = g_xb;   }
    else if (i < SX4 + SU4)        { j = i - SX4;             f = u[j];   dst = g_ub;   }
    else if (i < SX4 + SU4 + SW4)  { j = i - SX4 - SU4;       f = win[j]; dst = g_winb; }
    else if (i < TOTAL4)           { j = i - SX4 - SU4 - SW4; f = wr[j];  dst = g_wrb;  }
    else return;
    __nv_bfloat162* o = reinterpret_cast<__nv_bfloat162*>(dst) + j * 2;
    o[0] = __floats2bfloat162_rn(f.x, f.y);
    o[1] = __floats2bfloat162_rn(f.z, f.w);
}

// ---------------------------------------------------------------------------
// Fused GEMM + SfaRNN epilogue (128x128 tile, 2 CTAs/SM, ks-staggered warps)
// ---------------------------------------------------------------------------
__global__ void __launch_bounds__(NTHREADS, 2)
sfa_rnn_kernel(const float* __restrict__ u,
               const float* __restrict__ v,
               const float* __restrict__ bias,
               float* __restrict__ out) {
    extern __shared__ char smem[];
    const uint32_t sbase = smem_u32(smem);

    const int tid  = threadIdx.x;
    const int wid  = tid >> 5;
    const int lane = tid & 31;
    const int lq   = lane >> 2;
    const int lr   = lane & 3;
    const int wm   = wid & 1;    // M half (64 rows)
    const int wn   = wid >> 1;   // N group of 32 cols (0..3)
    const uint32_t kphase = (uint32_t)(wid & 3);  // per-warp ks rotation

    const int nb = blockIdx.x * BN;
    const int mb = blockIdx.y * BM;

    // ---------------- producer geometry ----------------
    const int rbase = tid >> 3;  // 0..31
    const int c16   = tid & 7;   // 16B chunk within 128B row
    const uint32_t swbase =
        (uint32_t)rbase * 128u + ((uint32_t)(c16 ^ (rbase & 7)) << 4);

    const __nv_bfloat16* gax = g_xb   + (size_t)(mb + rbase) * DIN   + c16 * 8;
    const __nv_bfloat16* gau = g_ub   + (size_t)(mb + rbase) * H_DIM + c16 * 8;
    const __nv_bfloat16* gbw = g_winb + (size_t)(nb + rbase) * DIN   + c16 * 8;
    const __nv_bfloat16* gbr = g_wrb  + (size_t)(nb + rbase) * H_DIM + c16 * 8;

    auto issue_chunk = [&](int k) {
        const int s = k % STAGES;
        const uint32_t sA = sbase + s * STAGE_BYTES;
        const uint32_t sB = sA + A_BYTES;
        if (k < NKX) {
            const __nv_bfloat16* ga = gax + k * BKE;
            const __nv_bfloat16* gb = gbw + k * BKE;
#pragma unroll
            for (int i = 0; i < 4; i++)
                cp_async16(sA + swbase + i * 4096u, ga + (size_t)i * 32 * DIN);
#pragma unroll
            for (int i = 0; i < 4; i++)
                cp_async16(sB + swbase + i * 4096u, gb + (size_t)i * 32 * DIN);
        } else {
            const __nv_bfloat16* ga = gau + (k - NKX) * BKE;
            const __nv_bfloat16* gb = gbr + (k - NKX) * BKE;
#pragma unroll
            for (int i = 0; i < 4; i++)
                cp_async16(sA + swbase + i * 4096u, ga + (size_t)i * 32 * H_DIM);
#pragma unroll
            for (int i = 0; i < 4; i++)
                cp_async16(sB + swbase + i * 4096u, gb + (size_t)i * 32 * H_DIM);
        }
    };

    // ---------------- consumer geometry (ldmatrix) ----------------
    const uint32_t r8   = (uint32_t)(lane & 7);
    const uint32_t a_hi = (uint32_t)(lane >> 4);
    const uint32_t a_m8 = (uint32_t)(((lane >> 3) & 1) << 3);
    const uint32_t b_hi = (uint32_t)((lane >> 3) & 1);
    const uint32_t b_n8 = (uint32_t)((lane >> 4) << 3);

    uint32_t baseA[4];
#pragma unroll
    for (int mi = 0; mi < 4; mi++)
        baseA[mi] = (uint32_t)(wm * 64 + mi * 16) * 128u + (r8 + a_m8) * 128u;
    uint32_t baseB[2];
#pragma unroll
    for (int ni2 = 0; ni2 < 2; ni2++)
        baseB[ni2] = (uint32_t)(wn * 32 + ni2 * 16) * 128u + (r8 + b_n8) * 128u;

    float acc[4][4][4];
#pragma unroll
    for (int mi = 0; mi < 4; mi++)
#pragma unroll
        for (int ni = 0; ni < 4; ni++)
#pragma unroll
            for (int r = 0; r < 4; r++) acc[mi][ni][r] = 0.0f;

    // ---------------- prologue ----------------
    issue_chunk(0); cp_commit();
    issue_chunk(1); cp_commit();

    // ---------------- mainloop ----------------
#pragma unroll 1
    for (int k = 0; k < NK; k++) {
        cp_wait<1>();
        __syncthreads();
        if (k + 2 < NK) issue_chunk(k + 2);
        cp_commit();

        const int s = k % STAGES;
        const uint32_t sA = sbase + s * STAGE_BYTES;
        const uint32_t sB = sA + A_BYTES;

#pragma unroll
        for (int kss = 0; kss < 4; kss++) {
            // per-warp phase rotation: warps start at different ks sub-steps,
            // so LDSM bursts of one phase group overlap MMA bursts of others
            const uint32_t ks = ((uint32_t)kss + kphase) & 3u;
            const uint32_t offA = ((2u * ks + a_hi) ^ r8) << 4;
            const uint32_t offB = ((2u * ks + b_hi) ^ r8) << 4;

            uint32_t a[4][4];
#pragma unroll
            for (int mi = 0; mi < 4; mi++) LDSM_X4(a[mi], sA + baseA[mi] + offA);
            uint32_t b[2][4];
#pragma unroll
            for (int ni2 = 0; ni2 < 2; ni2++) LDSM_X4(b[ni2], sB + baseB[ni2] + offB);

#pragma unroll
            for (int mi = 0; mi < 4; mi++)
#pragma unroll
                for (int ni = 0; ni < 4; ni++)
                    mma_bf16(acc[mi][ni], a[mi],
                             b[ni >> 1][(ni & 1) * 2 + 0],
                             b[ni >> 1][(ni & 1) * 2 + 1]);
        }
    }

    // ---------------- fused epilogue ----------------
    const float cu  = 1.0f - (1.0f / 10.0f);
    const float au  = 1.0f / 10.0f;
    const float cv  = 1.0f - (1.0f / 150.0f);
    const float cvm = 10.0f / 150.0f;
    const size_t OUTV = (size_t)B_DIM * H_DIM;

#pragma unroll
    for (int mi = 0; mi < 4; mi++) {
#pragma unroll
        for (int ni = 0; ni < 4; ni++) {
            const int r0 = mb + wm * 64 + mi * 16 + lq;
            const int c  = nb + wn * 32 + ni * 8 + lr * 2;
            const float2 bn = *reinterpret_cast<const float2*>(bias + c);
#pragma unroll
            for (int h = 0; h < 2; h++) {
                const size_t off = (size_t)(r0 + 8 * h) * H_DIM + c;
                const float2 uu = *reinterpret_cast<const float2*>(u + off);
                const float2 vv = *reinterpret_cast<const float2*>(v + off);
                const float g0 = acc[mi][ni][2 * h + 0];
                const float g1 = acc[mi][ni][2 * h + 1];
                const float vn0 = fmaxf(cv * vv.x + cvm * uu.x, 0.0f);
                const float vn1 = fmaxf(cv * vv.y + cvm * uu.y, 0.0f);
                const float un0 = fmaxf(cu * uu.x + au * (g0 + bn.x - vn0), 0.0f);
                const float un1 = fmaxf(cu * uu.y + au * (g1 + bn.y - vn1), 0.0f);
                *reinterpret_cast<float2*>(out + off)        = make_float2(un0, un1);
                *reinterpret_cast<float2*>(out + OUTV + off) = make_float2(vn0, vn1);
            }
        }
    }
}

extern "C" void kernel_launch(void* const* d_in, const int* in_sizes, int n_in,
                              void* d_out, int out_size) {
    (void)in_sizes; (void)n_in; (void)out_size;
    const float* x    = (const float*)d_in[0];
    const float* u    = (const float*)d_in[1];
    const float* v    = (const float*)d_in[2];
    const float* win  = (const float*)d_in[3];
    const float* wr   = (const float*)d_in[4];
    const float* bias = (const float*)d_in[5];
    float* out = (float*)d_out;

    // 1) convert inputs to bf16 scratch
    const int cb = (int)(TOTAL4 / 256);  // 30720 blocks, exact
    convert_kernel<<<cb, 256>>>((const float4*)x, (const float4*)u,
                                (const float4*)win, (const float4*)wr);

    // 2) fused GEMM + epilogue
    cudaFuncSetAttribute(sfa_rnn_kernel,
                         cudaFuncAttributeMaxDynamicSharedMemorySize, SMEM_TOTAL);
    dim3 grid(H_DIM / BN, B_DIM / BM);  // (16, 64) = 1024 CTAs
    sfa_rnn_kernel<<<grid, NTHREADS, SMEM_TOTAL>>>(u, v, bias, out);
}